// round 10
// baseline (speedup 1.0000x reference)
#include <cuda_runtime.h>
#include <cuda_fp16.h>
#include <cstdint>

// ============================================================================
// ModulatedConv1d (B=16, C=512, L=2048, K=3, pad=1) — plain sm_100 path
// SINGLE persistent kernel (296 CTAs = 2/SM, all co-resident), 3 phases
// separated by in-kernel grid barriers (monotonic ticket/epoch, replay-safe):
//   A: s[b,i] = MOD_SCALE*style@modW^T + bias ;  W -> fp16 swizzled g_w2, wsqT
//   B: x -> fp16(s*x) transposed+swizzled g_x2 ; gain[b,o] ; boundary zeros
//   C: conv GEMM: dynamic tiles, 3-stage cp.async.bulk ring rolling across
//      tile boundaries, ldmatrix + reg-double-buffered mma.m16n8k16 f16->f32
// ============================================================================

#define MOD_SCALE_F 0.04419417382415922f   /* 1/sqrt(512)   */
#define SCALE_F     0.014731391274719739f  /* 1/sqrt(512*9) */

#define NTHREADS 256
#define NCTAS    296
#define NTILES   1024
// Stage: A = 3 taps x 128 rows x 64B = 24576 ; X = 130 rows x 64B = 8320
#define A_TAP    8192
#define X_OFF    24576
#define STAGE    32896
#define NSTAGE   3
#define STAGE0   64
#define SMEM_TOTAL (STAGE0 + NSTAGE * STAGE)   /* 98752 */

// static device scratch (no runtime allocation)
__device__ float  g_s[16 * 512];
__device__ float  g_wsqT[512 * 512];          // [i][o]
__device__ float  g_gain[16 * 512];
__device__ int    g_tile_ctr;                 // reset by barrier-2 releaser
__device__ int    g_bar_ctr;                  // monotonic arrivals
__device__ int    g_bar_rel;                  // monotonic epoch releases
// W chunk-major: [ic(16)][otile(4)][tap(3)][o(128)][c'(4) x 8 halves]
__device__ __half g_w2[16 * 4 * 3 * 128 * 32];
// X chunk-major: [b(16)][ic(16)][R(2056)][c'(4) x 8 halves],  R = l + 1
__device__ __half g_x2[(size_t)16 * 16 * 2056 * 32];

// ---------------------------------------------------------------------------
__device__ __forceinline__ uint32_t smem_u32(const void* p) {
    uint32_t a;
    asm("{ .reg .u64 t; cvta.to.shared.u64 t, %1; cvt.u32.u64 %0, t; }" : "=r"(a) : "l"(p));
    return a;
}
__device__ __forceinline__ void bulk_cp(uint32_t dst, const void* src, uint32_t bytes,
                                        uint32_t mbar) {
    asm volatile(
        "cp.async.bulk.shared::cluster.global.mbarrier::complete_tx::bytes "
        "[%0], [%1], %2, [%3];"
        :: "r"(dst), "l"(src), "r"(bytes), "r"(mbar) : "memory");
}
__device__ __forceinline__ void mbar_init(uint32_t mbar, uint32_t cnt) {
    asm volatile("mbarrier.init.shared.b64 [%0], %1;" :: "r"(mbar), "r"(cnt) : "memory");
}
__device__ __forceinline__ void mbar_expect_tx(uint32_t mbar, uint32_t tx) {
    asm volatile("mbarrier.arrive.expect_tx.shared.b64 _, [%0], %1;"
                 :: "r"(mbar), "r"(tx) : "memory");
}
__device__ __forceinline__ void mbar_wait(uint32_t mbar, uint32_t parity) {
    uint32_t done;
    asm volatile("{\n\t.reg .pred p;\n\t"
        "mbarrier.try_wait.parity.acquire.cta.shared::cta.b64 p, [%1], %2;\n\t"
        "selp.b32 %0, 1, 0, p;\n\t}" : "=r"(done) : "r"(mbar), "r"(parity) : "memory");
    if (!done) {
        asm volatile("{\n\t.reg .pred P1;\n\t"
            "WAIT_LOOP_%=:\n\t"
            "mbarrier.try_wait.parity.acquire.cta.shared::cta.b64 P1, [%0], %1, 0x989680;\n\t"
            "@P1 bra.uni WAIT_DONE_%=;\n\t"
            "bra.uni WAIT_LOOP_%=;\n\t"
            "WAIT_DONE_%=:\n\t}" :: "r"(mbar), "r"(parity) : "memory");
    }
}
__device__ __forceinline__ void ldsm4(uint32_t* r, uint32_t addr) {
    asm volatile("ldmatrix.sync.aligned.m8n8.x4.shared.b16 {%0,%1,%2,%3}, [%4];"
        : "=r"(r[0]), "=r"(r[1]), "=r"(r[2]), "=r"(r[3]) : "r"(addr));
}
__device__ __forceinline__ void mma_f16(float* c, const uint32_t* a, uint32_t b0, uint32_t b1) {
    asm volatile(
        "mma.sync.aligned.m16n8k16.row.col.f32.f16.f16.f32 "
        "{%0,%1,%2,%3}, {%4,%5,%6,%7}, {%8,%9}, {%0,%1,%2,%3};"
        : "+f"(c[0]), "+f"(c[1]), "+f"(c[2]), "+f"(c[3])
        : "r"(a[0]), "r"(a[1]), "r"(a[2]), "r"(a[3]), "r"(b0), "r"(b1));
}

// Grid barrier: monotonic ticket/epoch; safe across graph replays.
// All NCTAS CTAs are co-resident by construction (2 CTAs/SM x 148 SMs).
__device__ __forceinline__ void grid_barrier(bool reset_tiles) {
    __syncthreads();
    if (threadIdx.x == 0) {
        __threadfence();
        int ticket = atomicAdd(&g_bar_ctr, 1);
        int epoch = ticket / NCTAS + 1;
        if ((ticket % NCTAS) == (NCTAS - 1)) {
            if (reset_tiles) g_tile_ctr = 0;
            __threadfence();
            atomicAdd(&g_bar_rel, 1);
        } else {
            int r;
            do {
                asm volatile("ld.acquire.gpu.global.s32 %0, [%1];"
                             : "=r"(r) : "l"(&g_bar_rel));
                if (r < epoch) __nanosleep(64);
            } while (r < epoch);
        }
    }
    __syncthreads();
}

// ---------------------------------------------------------------------------
__global__ void __launch_bounds__(NTHREADS, 2)
conv_fused(const float* __restrict__ x, const float* __restrict__ style,
           const float* __restrict__ w, const float* __restrict__ modw,
           const float* __restrict__ bias, float* __restrict__ out) {
    extern __shared__ char smem[];
    const uint32_t sb = smem_u32(smem);
    int* s_tile = (int*)(smem + 32);             // [2] ping-pong next-tile slots

    const int tid  = threadIdx.x;
    const int warp = tid >> 5;
    const int lane = tid & 31;

    // ==================== PHASE A: s + W transform ====================
    {
        // s[b,i]: one warp per (b,i) item
        int gw = blockIdx.x * 8 + warp;
        for (int item = gw; item < 8192; item += NCTAS * 8) {
            int b = item >> 9, i = item & 511;
            const float* mrow = modw + (size_t)i * 512;
            const float* srow = style + (size_t)b * 512;
            float acc = 0.f;
            #pragma unroll
            for (int t = 0; t < 16; t++) acc += mrow[lane + t * 32] * srow[lane + t * 32];
            #pragma unroll
            for (int o = 16; o; o >>= 1) acc += __shfl_xor_sync(0xFFFFFFFFu, acc, o);
            if (lane == 0) g_s[b * 512 + i] = acc * MOD_SCALE_F + bias[i];
        }
        // W transform: idx = o*512 + i
        for (int idx = blockIdx.x * NTHREADS + tid; idx < 262144; idx += NCTAS * NTHREADS) {
            int o = idx >> 9, i = idx & 511;
            float w0 = w[idx * 3 + 0];
            float w1 = w[idx * 3 + 1];
            float w2 = w[idx * 3 + 2];
            g_wsqT[i * 512 + o] = w0 * w0 + w1 * w1 + w2 * w2;
            int ic = i >> 5, c = (i >> 3) & 3, h = i & 7;
            int otile = o >> 7, o128 = o & 127;
            int cp = c ^ ((o128 >> 1) & 3);
            size_t base = ((size_t)((ic * 4 + otile) * 3) * 128 + o128) * 32 + cp * 8 + h;
            g_w2[base + 0 * 4096] = __float2half_rn(w0);
            g_w2[base + 1 * 4096] = __float2half_rn(w1);
            g_w2[base + 2 * 4096] = __float2half_rn(w2);
        }
    }
    grid_barrier(false);

    // ==================== PHASE B: X transform + gain + zeros ====================
    {
        float* smf = (float*)(smem + STAGE0);    // 64 x 33 floats, aliases ring
        for (int id = blockIdx.x; id < 8192; id += NCTAS) {
            int lt = id & 63, it = (id >> 6) & 7, b = id >> 9;
            int l0 = lt * 32, i0 = it * 64;
            const float* xb = x + ((size_t)b * 512) * 2048;

            if (lt == 0) {
                int ridx = tid >> 5, col = tid & 31;
                int R = (ridx == 0) ? 0 : (2048 + ridx);
                __half z = __float2half_rn(0.f);
                g_x2[((size_t)(b * 16 + it * 2 + 0) * 2056 + R) * 32 + col] = z;
                g_x2[((size_t)(b * 16 + it * 2 + 1) * 2056 + R) * 32 + col] = z;
            }
            if (lt == 1) {
                int oo = tid >> 2, q = tid & 3;
                int o = it * 64 + oo;
                const float* sp = g_s + b * 512;
                float accg = 0.f;
                #pragma unroll 4
                for (int i = q * 128; i < q * 128 + 128; i++) {
                    float sv = sp[i];
                    accg += sv * sv * g_wsqT[(size_t)i * 512 + o];
                }
                accg += __shfl_xor_sync(0xFFFFFFFFu, accg, 1);
                accg += __shfl_xor_sync(0xFFFFFFFFu, accg, 2);
                if (q == 0)
                    g_gain[b * 512 + o] = SCALE_F * rsqrtf(SCALE_F * SCALE_F * accg + 1e-8f);
            }

            #pragma unroll
            for (int r = 0; r < 8; r++) {
                int il = warp * 8 + r;
                float sv = g_s[b * 512 + i0 + il];
                smf[il * 33 + lane] = xb[(size_t)(i0 + il) * 2048 + l0 + lane] * sv;
            }
            __syncthreads();
            #pragma unroll
            for (int rr = 0; rr < 4; rr++) {
                int ll = warp * 4 + rr;
                int R = l0 + ll + 1;
                __half2 h = __floats2half2_rn(smf[(lane * 2) * 33 + ll],
                                              smf[(lane * 2 + 1) * 33 + ll]);
                int i = i0 + lane * 2;
                int ic = i >> 5, c = (i >> 3) & 3, hh = i & 7;
                int cp = c ^ ((R >> 1) & 3);
                *(__half2*)(g_x2 + ((size_t)(b * 16 + ic) * 2056 + R) * 32 + cp * 8 + hh) = h;
            }
            __syncthreads();
        }
    }
    grid_barrier(true);   // releaser resets g_tile_ctr before release

    // ==================== PHASE C: conv GEMM ====================
    const int mw = (warp & 3) * 32;
    const int nw = (warp >> 2) * 64;

    const int rowA = mw + (lane & 15);
    const uint32_t swa = (uint32_t)((rowA >> 1) & 3);
    const uint32_t cA  = (uint32_t)((lane >> 4) & 1);
    const uint32_t aAddr = (uint32_t)rowA * 64;
    const int rowB = nw + (lane & 7) + ((lane >> 4) << 3);
    const uint32_t cB = (uint32_t)((lane >> 3) & 1);
    uint32_t swb[3];
    #pragma unroll
    for (int t = 0; t < 3; t++) swb[t] = (uint32_t)(((rowB + t) >> 1) & 3);

    float acc[2][8][4];
    #pragma unroll
    for (int mi = 0; mi < 2; mi++)
        #pragma unroll
        for (int ni = 0; ni < 8; ni++)
            #pragma unroll
            for (int j = 0; j < 4; j++) acc[mi][ni][j] = 0.f;

    auto issue = [&](int t, int icn, int st) {
        int ot  = t & 3;
        int ll0 = ((t >> 2) & 15) * 128;
        int bb  = t >> 6;
        const __half* ws = g_w2 + (size_t)(icn * 4 + ot) * 12288;
        const __half* xs = g_x2 + ((size_t)(bb * 16 + icn) * 2056 + ll0) * 32;
        uint32_t sa = sb + STAGE0 + (uint32_t)st * STAGE;
        uint32_t mb = sb + (uint32_t)st * 8;
        mbar_expect_tx(mb, STAGE);
        bulk_cp(sa,         ws, 24576, mb);
        bulk_cp(sa + X_OFF, xs, 8320, mb);
    };

    int pt = 0, p_ic = 0, nt_reg = 0;

    if (tid == 0) {
        #pragma unroll
        for (int s = 0; s < NSTAGE; s++) mbar_init(sb + s * 8, 1);
    }
    __syncthreads();
    if (tid == 0) {
        int t0 = atomicAdd(&g_tile_ctr, 1);
        s_tile[0] = t0;
        pt = t0;
        if (t0 < NTILES) {
            issue(t0, 0, 0);
            issue(t0, 1, 1);
            issue(t0, 2, 2);
        }
        p_ic = 3;
    }
    __syncthreads();

    int tile  = s_tile[0];
    int tslot = 0;
    uint32_t cons = 0;

    #define AADR(base, s) ((base) + ((s) >> 1) * A_TAP + aAddr \
                          + ((((uint32_t)(((s) & 1) * 2)) + cA) ^ swa) * 16)
    #define BADR(base, s, np) ((base) + X_OFF + (uint32_t)(rowB + (np) * 16 + ((s) >> 1)) * 64 \
                          + ((((uint32_t)(((s) & 1) * 2)) + cB) ^ swb[(s) >> 1]) * 16)

    while (tile < NTILES) {
        for (int ic = 0; ic < 16; ic++) {
            const int st = (int)(cons % 3u);
            mbar_wait(sb + (uint32_t)st * 8, (cons / 3u) & 1u);

            const uint32_t base = sb + STAGE0 + (uint32_t)st * STAGE;

            uint32_t A0[2][4], A1[2][4], BF[2][4];
            ldsm4(A0[0], AADR(base, 0));
            ldsm4(A1[0], AADR(base, 0) + 16 * 64);
            ldsm4(BF[0], BADR(base, 0, 0));

            #pragma unroll
            for (int s = 0; s < 6; s++) {
                const int pa = s & 1;
                #pragma unroll
                for (int np = 0; np < 4; np++) {
                    const int pb = (s * 4 + np) & 1;
                    if (np < 3) {
                        ldsm4(BF[pb ^ 1], BADR(base, s, np + 1));
                    } else if (s < 5) {
                        ldsm4(A0[pa ^ 1], AADR(base, s + 1));
                        ldsm4(A1[pa ^ 1], AADR(base, s + 1) + 16 * 64);
                        ldsm4(BF[pb ^ 1], BADR(base, s + 1, 0));
                    }
                    mma_f16(acc[0][np * 2],     A0[pa], BF[pb][0], BF[pb][1]);
                    mma_f16(acc[1][np * 2],     A1[pa], BF[pb][0], BF[pb][1]);
                    mma_f16(acc[0][np * 2 + 1], A0[pa], BF[pb][2], BF[pb][3]);
                    mma_f16(acc[1][np * 2 + 1], A1[pa], BF[pb][2], BF[pb][3]);
                }
            }

            __syncthreads();

            if (tid == 0) {
                if (ic == 12) {
                    nt_reg = atomicAdd(&g_tile_ctr, 1);
                    s_tile[tslot ^ 1] = nt_reg;
                }
                if (p_ic == 16) { pt = nt_reg; p_ic = 0; }
                if (pt < NTILES) issue(pt, p_ic, st);
                p_ic++;
            }
            cons++;
        }

        // epilogue for `tile` (next tile's loads already in flight)
        {
            const int obase = (tile & 3) * 128;
            const int l0    = ((tile >> 2) & 15) * 128;
            const int b     = tile >> 6;
            const int r0l = mw + (lane >> 2);
            const float* gg = g_gain + b * 512 + obase + r0l;
            const float g00 = gg[0];
            const float g01 = gg[8];
            const float g10 = gg[16];
            const float g11 = gg[24];
            const int r0 = obase + r0l;
            const int lcol = l0 + nw + (lane & 3) * 2;

            #pragma unroll
            for (int mi = 0; mi < 2; mi++) {
                const int ra = r0 + mi * 16;
                const float ga = mi ? g10 : g00;
                const float gb = mi ? g11 : g01;
                float* outa = out + ((size_t)(b * 512 + ra)) * 2048 + lcol;
                float* outb = out + ((size_t)(b * 512 + ra + 8)) * 2048 + lcol;
                #pragma unroll
                for (int ni = 0; ni < 8; ni++) {
                    float2 va, vb;
                    va.x = acc[mi][ni][0] * ga;
                    va.y = acc[mi][ni][1] * ga;
                    vb.x = acc[mi][ni][2] * gb;
                    vb.y = acc[mi][ni][3] * gb;
                    *(float2*)(outa + ni * 8) = va;
                    *(float2*)(outb + ni * 8) = vb;
                    acc[mi][ni][0] = 0.f;
                    acc[mi][ni][1] = 0.f;
                    acc[mi][ni][2] = 0.f;
                    acc[mi][ni][3] = 0.f;
                }
            }
        }

        tile = s_tile[tslot ^ 1];
        tslot ^= 1;
    }
    #undef AADR
    #undef BADR
}

// ---------------------------------------------------------------------------
extern "C" void kernel_launch(void* const* d_in, const int* in_sizes, int n_in,
                              void* d_out, int out_size) {
    const float* x      = (const float*)d_in[0];
    const float* style  = (const float*)d_in[1];
    const float* weight = (const float*)d_in[2];
    const float* modw   = (const float*)d_in[3];
    const float* bias   = (const float*)d_in[4];
    float* out = (float*)d_out;

    cudaFuncSetAttribute(conv_fused, cudaFuncAttributeMaxDynamicSharedMemorySize, SMEM_TOTAL);

    conv_fused<<<NCTAS, NTHREADS, SMEM_TOTAL>>>(x, style, weight, modw, bias, out);
}

// round 11
// speedup vs baseline: 1.2931x; 1.2931x over previous
#include <cuda_runtime.h>
#include <cuda_fp16.h>
#include <cstdint>

// ============================================================================
// ModulatedConv1d (B=16, C=512, L=2048, K=3, pad=1) — plain sm_100 path
//   s[b,i]    = MOD_SCALE * style[b,:] @ modW[i,:] + bias[i]
//   gain[b,o] = SCALE * rsqrt(SCALE^2 * sum_i s^2 * wsq[o,i] + 1e-8)
//   out[b,o,l]= gain[b,o] * sum_{i,k} W[o,i,k] * s[b,i] * x[b,i,l+k-1]
// 3 kernels: prep_sw (s + W->fp16 swizzled + wsqT), prep_xt (x->fp16(s*x)
// transposed+swizzled, + gain + boundary zeros), conv_main (persistent 296
// CTAs, dynamic tiles, 3-stage cp.async.bulk ring rolling across tiles,
// ldmatrix + reg-double-buffered mma.m16n8k16; consumer->producer handoff via
// empty-mbarriers instead of per-chunk __syncthreads).
// ============================================================================

#define MOD_SCALE_F 0.04419417382415922f   /* 1/sqrt(512)   */
#define SCALE_F     0.014731391274719739f  /* 1/sqrt(512*9) */

#define NTHREADS 256
#define NCTAS    296
#define NTILES   1024
// Stage: A = 3 taps x 128 rows x 64B = 24576 ; X = 130 rows x 64B = 8320
#define A_TAP    8192
#define X_OFF    24576
#define STAGE    32896
#define NSTAGE   3
#define STAGE0   64        /* full mbars @0..23, empty mbars @24..47, s_tile @48 */
#define SMEM_TOTAL (STAGE0 + NSTAGE * STAGE)   /* 98752 */

// static device scratch (no runtime allocation)
__device__ float  g_s[16 * 512];
__device__ float  g_wsqT[512 * 512];          // [i][o]
__device__ float  g_gain[16 * 512];
__device__ int    g_tile_ctr;                 // reset by prep_sw each replay
// W chunk-major: [ic(16)][otile(4)][tap(3)][o(128)][c'(4) x 8 halves]
__device__ __half g_w2[16 * 4 * 3 * 128 * 32];
// X chunk-major: [b(16)][ic(16)][R(2056)][c'(4) x 8 halves],  R = l + 1
__device__ __half g_x2[(size_t)16 * 16 * 2056 * 32];

// ---------------------------------------------------------------------------
__device__ __forceinline__ uint32_t smem_u32(const void* p) {
    uint32_t a;
    asm("{ .reg .u64 t; cvta.to.shared.u64 t, %1; cvt.u32.u64 %0, t; }" : "=r"(a) : "l"(p));
    return a;
}
__device__ __forceinline__ void bulk_cp(uint32_t dst, const void* src, uint32_t bytes,
                                        uint32_t mbar) {
    asm volatile(
        "cp.async.bulk.shared::cluster.global.mbarrier::complete_tx::bytes "
        "[%0], [%1], %2, [%3];"
        :: "r"(dst), "l"(src), "r"(bytes), "r"(mbar) : "memory");
}
__device__ __forceinline__ void mbar_init(uint32_t mbar, uint32_t cnt) {
    asm volatile("mbarrier.init.shared.b64 [%0], %1;" :: "r"(mbar), "r"(cnt) : "memory");
}
__device__ __forceinline__ void mbar_expect_tx(uint32_t mbar, uint32_t tx) {
    asm volatile("mbarrier.arrive.expect_tx.shared.b64 _, [%0], %1;"
                 :: "r"(mbar), "r"(tx) : "memory");
}
__device__ __forceinline__ void mbar_arrive(uint32_t mbar) {
    asm volatile("mbarrier.arrive.shared.b64 _, [%0];" :: "r"(mbar) : "memory");
}
__device__ __forceinline__ void mbar_wait(uint32_t mbar, uint32_t parity) {
    uint32_t done;
    asm volatile("{\n\t.reg .pred p;\n\t"
        "mbarrier.try_wait.parity.acquire.cta.shared::cta.b64 p, [%1], %2;\n\t"
        "selp.b32 %0, 1, 0, p;\n\t}" : "=r"(done) : "r"(mbar), "r"(parity) : "memory");
    if (!done) {
        asm volatile("{\n\t.reg .pred P1;\n\t"
            "WAIT_LOOP_%=:\n\t"
            "mbarrier.try_wait.parity.acquire.cta.shared::cta.b64 P1, [%0], %1, 0x989680;\n\t"
            "@P1 bra.uni WAIT_DONE_%=;\n\t"
            "bra.uni WAIT_LOOP_%=;\n\t"
            "WAIT_DONE_%=:\n\t}" :: "r"(mbar), "r"(parity) : "memory");
    }
}
__device__ __forceinline__ void ldsm4(uint32_t* r, uint32_t addr) {
    asm volatile("ldmatrix.sync.aligned.m8n8.x4.shared.b16 {%0,%1,%2,%3}, [%4];"
        : "=r"(r[0]), "=r"(r[1]), "=r"(r[2]), "=r"(r[3]) : "r"(addr));
}
__device__ __forceinline__ void mma_f16(float* c, const uint32_t* a, uint32_t b0, uint32_t b1) {
    asm volatile(
        "mma.sync.aligned.m16n8k16.row.col.f32.f16.f16.f32 "
        "{%0,%1,%2,%3}, {%4,%5,%6,%7}, {%8,%9}, {%0,%1,%2,%3};"
        : "+f"(c[0]), "+f"(c[1]), "+f"(c[2]), "+f"(c[3])
        : "r"(a[0]), "r"(a[1]), "r"(a[2]), "r"(a[3]), "r"(b0), "r"(b1));
}

// ---------------------------------------------------------------------------
// prep_sw: s (warp per item, style/modw read via L2) + W transform. grid 1024.
// ---------------------------------------------------------------------------
__global__ void prep_sw(const float* __restrict__ style, const float* __restrict__ modw,
                        const float* __restrict__ bias, const float* __restrict__ w) {
    if (blockIdx.x == 0 && threadIdx.x == 0) g_tile_ctr = 0;   // replay-safe reset
    const int warp = threadIdx.x >> 5, lane = threadIdx.x & 31;

    // s part: 8192 items, one per warp
    {
        int item = blockIdx.x * 8 + warp;
        int b = item >> 9, i = item & 511;
        const float* mrow = modw + (size_t)i * 512;
        const float* srow = style + (size_t)b * 512;
        float acc = 0.f;
        #pragma unroll
        for (int t = 0; t < 16; t++) acc += mrow[lane + t * 32] * srow[lane + t * 32];
        #pragma unroll
        for (int o = 16; o; o >>= 1) acc += __shfl_xor_sync(0xFFFFFFFFu, acc, o);
        if (lane == 0) g_s[b * 512 + i] = acc * MOD_SCALE_F + bias[i];
    }

    // W part: idx = o*512 + i
    {
        int idx = blockIdx.x * 256 + threadIdx.x;
        int o = idx >> 9, i = idx & 511;
        float w0 = w[idx * 3 + 0];
        float w1 = w[idx * 3 + 1];
        float w2 = w[idx * 3 + 2];
        g_wsqT[i * 512 + o] = w0 * w0 + w1 * w1 + w2 * w2;
        int ic = i >> 5, c = (i >> 3) & 3, h = i & 7;
        int otile = o >> 7, o128 = o & 127;
        int cp = c ^ ((o128 >> 1) & 3);
        size_t base = ((size_t)((ic * 4 + otile) * 3) * 128 + o128) * 32 + cp * 8 + h;
        g_w2[base + 0 * 4096] = __float2half_rn(w0);
        g_w2[base + 1 * 4096] = __float2half_rn(w1);
        g_w2[base + 2 * 4096] = __float2half_rn(w2);
    }
}

// ---------------------------------------------------------------------------
// prep_xt v2: 64(i) x 64(l) tiles, float2 loads. grid (32, 8, 16) = 4096.
// Fused boundary zeros (lt==0) and gain (lt==1).
// ---------------------------------------------------------------------------
__global__ void prep_xt(const float* __restrict__ x) {
    __shared__ float smf[64 * 67];
    const int lt = blockIdx.x;   // 0..31
    const int it = blockIdx.y;   // 0..7
    const int b  = blockIdx.z;   // 0..15
    const int warp = threadIdx.x >> 5, lane = threadIdx.x & 31;
    const int l0 = lt * 64, i0 = it * 64;
    const float* xb = x + ((size_t)b * 512) * 2048;

    if (lt == 0) {
        int ridx = threadIdx.x >> 5, col = threadIdx.x & 31;
        int R = (ridx == 0) ? 0 : (2048 + ridx);
        __half z = __float2half_rn(0.f);
        g_x2[((size_t)(b * 16 + it * 2 + 0) * 2056 + R) * 32 + col] = z;
        g_x2[((size_t)(b * 16 + it * 2 + 1) * 2056 + R) * 32 + col] = z;
    }
    if (lt == 1) {
        int oo = threadIdx.x >> 2, q = threadIdx.x & 3;
        int o = it * 64 + oo;
        const float* sp = g_s + b * 512;
        float accg = 0.f;
        #pragma unroll 4
        for (int i = q * 128; i < q * 128 + 128; i++) {
            float sv = sp[i];
            accg += sv * sv * g_wsqT[(size_t)i * 512 + o];
        }
        accg += __shfl_xor_sync(0xFFFFFFFFu, accg, 1);
        accg += __shfl_xor_sync(0xFFFFFFFFu, accg, 2);
        if (q == 0)
            g_gain[b * 512 + o] = SCALE_F * rsqrtf(SCALE_F * SCALE_F * accg + 1e-8f);
    }

    // load 64 rows x 64 floats (scaled)
    #pragma unroll
    for (int r = 0; r < 8; r++) {
        int il = warp * 8 + r;
        float sv = g_s[b * 512 + i0 + il];
        float2 v = *(const float2*)(xb + (size_t)(i0 + il) * 2048 + l0 + lane * 2);
        smf[il * 67 + lane * 2]     = v.x * sv;
        smf[il * 67 + lane * 2 + 1] = v.y * sv;
    }
    __syncthreads();
    // transpose-store: warp handles 8 ll columns
    #pragma unroll
    for (int rr = 0; rr < 8; rr++) {
        int ll = warp * 8 + rr;
        int R = l0 + ll + 1;
        __half2 h = __floats2half2_rn(smf[(lane * 2) * 67 + ll],
                                      smf[(lane * 2 + 1) * 67 + ll]);
        int i = i0 + lane * 2;
        int ic = i >> 5, c = (i >> 3) & 3, hh = i & 7;
        int cp = c ^ ((R >> 1) & 3);
        *(__half2*)(g_x2 + ((size_t)(b * 16 + ic) * 2056 + R) * 32 + cp * 8 + hh) = h;
    }
}

// ---------------------------------------------------------------------------
// Main: persistent 296 CTAs (2/SM), dynamic tiles. Tile = 128(o) x 128(l).
// 256 threads (8 warps, 4m x 2n). 3-stage bulk ring continuous across tiles.
// Consumers ARRIVE on empty-mbarriers (no per-chunk __syncthreads); only the
// tid0 producer WAITS on empty before refilling a stage.
// ---------------------------------------------------------------------------
__global__ void __launch_bounds__(NTHREADS, 2)
conv_main(float* __restrict__ out) {
    extern __shared__ char smem[];
    const uint32_t sb = smem_u32(smem);
    int* s_tile = (int*)(smem + 48);             // [2] ping-pong next-tile slots

    const int tid  = threadIdx.x;
    const int warp = tid >> 5;
    const int lane = tid & 31;
    const int mw = (warp & 3) * 32;
    const int nw = (warp >> 2) * 64;

    // tile-independent fragment geometry (swizzled 64B rows)
    const int rowA = mw + (lane & 15);
    const uint32_t swa = (uint32_t)((rowA >> 1) & 3);
    const uint32_t cA  = (uint32_t)((lane >> 4) & 1);
    const uint32_t aAddr = (uint32_t)rowA * 64;
    const int rowB = nw + (lane & 7) + ((lane >> 4) << 3);
    const uint32_t cB = (uint32_t)((lane >> 3) & 1);
    uint32_t swb[3];
    #pragma unroll
    for (int t = 0; t < 3; t++) swb[t] = (uint32_t)(((rowB + t) >> 1) & 3);

    float acc[2][8][4];
    #pragma unroll
    for (int mi = 0; mi < 2; mi++)
        #pragma unroll
        for (int ni = 0; ni < 8; ni++)
            #pragma unroll
            for (int j = 0; j < 4; j++) acc[mi][ni][j] = 0.f;

    auto issue = [&](int t, int icn, int st) {
        int ot  = t & 3;
        int ll0 = ((t >> 2) & 15) * 128;
        int bb  = t >> 6;
        const __half* ws = g_w2 + (size_t)(icn * 4 + ot) * 12288;
        const __half* xs = g_x2 + ((size_t)(bb * 16 + icn) * 2056 + ll0) * 32;
        uint32_t sa = sb + STAGE0 + (uint32_t)st * STAGE;
        uint32_t mb = sb + (uint32_t)st * 8;      // full barrier
        mbar_expect_tx(mb, STAGE);
        bulk_cp(sa,         ws, 24576, mb);
        bulk_cp(sa + X_OFF, xs, 8320, mb);
    };

    int pt = 0, p_ic = 0, nt_reg = 0;
    uint32_t eph0 = 0, eph1 = 0, eph2 = 0;        // empty-barrier parities (tid0)

    if (tid == 0) {
        #pragma unroll
        for (int s = 0; s < NSTAGE; s++) {
            mbar_init(sb + s * 8, 1);             // full
            mbar_init(sb + 24 + s * 8, NTHREADS); // empty
        }
    }
    __syncthreads();
    if (tid == 0) {
        int t0 = atomicAdd(&g_tile_ctr, 1);
        s_tile[0] = t0;
        pt = t0;
        if (t0 < NTILES) {
            issue(t0, 0, 0);
            issue(t0, 1, 1);
            issue(t0, 2, 2);
        }
        p_ic = 3;
    }
    __syncthreads();

    int tile  = s_tile[0];
    int tslot = 0;
    uint32_t cons = 0;

    #define AADR(base, s) ((base) + ((s) >> 1) * A_TAP + aAddr \
                          + ((((uint32_t)(((s) & 1) * 2)) + cA) ^ swa) * 16)
    #define BADR(base, s, np) ((base) + X_OFF + (uint32_t)(rowB + (np) * 16 + ((s) >> 1)) * 64 \
                          + ((((uint32_t)(((s) & 1) * 2)) + cB) ^ swb[(s) >> 1]) * 16)

    while (tile < NTILES) {
        for (int ic = 0; ic < 16; ic++) {
            const int st = (int)(cons % 3u);
            mbar_wait(sb + (uint32_t)st * 8, (cons / 3u) & 1u);

            const uint32_t base = sb + STAGE0 + (uint32_t)st * STAGE;

            uint32_t A0[2][4], A1[2][4], BF[2][4];
            ldsm4(A0[0], AADR(base, 0));
            ldsm4(A1[0], AADR(base, 0) + 16 * 64);
            ldsm4(BF[0], BADR(base, 0, 0));

            #pragma unroll
            for (int s = 0; s < 6; s++) {
                const int pa = s & 1;
                #pragma unroll
                for (int np = 0; np < 4; np++) {
                    const int pb = (s * 4 + np) & 1;
                    if (np < 3) {
                        ldsm4(BF[pb ^ 1], BADR(base, s, np + 1));
                    } else if (s < 5) {
                        ldsm4(A0[pa ^ 1], AADR(base, s + 1));
                        ldsm4(A1[pa ^ 1], AADR(base, s + 1) + 16 * 64);
                        ldsm4(BF[pb ^ 1], BADR(base, s + 1, 0));
                    }
                    mma_f16(acc[0][np * 2],     A0[pa], BF[pb][0], BF[pb][1]);
                    mma_f16(acc[1][np * 2],     A1[pa], BF[pb][0], BF[pb][1]);
                    mma_f16(acc[0][np * 2 + 1], A0[pa], BF[pb][2], BF[pb][3]);
                    mma_f16(acc[1][np * 2 + 1], A1[pa], BF[pb][2], BF[pb][3]);
                }
            }

            // done reading stage st -> signal producer (non-blocking)
            mbar_arrive(sb + 24 + (uint32_t)st * 8);

            if (ic == 12 && tid == 0) {
                nt_reg = atomicAdd(&g_tile_ctr, 1);
                s_tile[tslot ^ 1] = nt_reg;
            }
            if (ic == 13) __syncthreads();        // publish s_tile

            if (tid == 0) {
                if (p_ic == 16) { pt = nt_reg; p_ic = 0; }
                if (pt < NTILES) {
                    uint32_t emb = sb + 24 + (uint32_t)st * 8;
                    uint32_t ep = (st == 0) ? eph0 : (st == 1) ? eph1 : eph2;
                    mbar_wait(emb, ep);
                    if (st == 0) eph0 ^= 1; else if (st == 1) eph1 ^= 1; else eph2 ^= 1;
                    issue(pt, p_ic, st);
                }
                p_ic++;
            }
            cons++;
        }

        // epilogue for `tile` (next tile's loads already in flight)
        {
            const int obase = (tile & 3) * 128;
            const int l0    = ((tile >> 2) & 15) * 128;
            const int b     = tile >> 6;
            const int r0l = mw + (lane >> 2);
            const float* gg = g_gain + b * 512 + obase + r0l;
            const float g00 = gg[0];
            const float g01 = gg[8];
            const float g10 = gg[16];
            const float g11 = gg[24];
            const int r0 = obase + r0l;
            const int lcol = l0 + nw + (lane & 3) * 2;

            #pragma unroll
            for (int mi = 0; mi < 2; mi++) {
                const int ra = r0 + mi * 16;
                const float ga = mi ? g10 : g00;
                const float gb = mi ? g11 : g01;
                float* outa = out + ((size_t)(b * 512 + ra)) * 2048 + lcol;
                float* outb = out + ((size_t)(b * 512 + ra + 8)) * 2048 + lcol;
                #pragma unroll
                for (int ni = 0; ni < 8; ni++) {
                    float2 va, vb;
                    va.x = acc[mi][ni][0] * ga;
                    va.y = acc[mi][ni][1] * ga;
                    vb.x = acc[mi][ni][2] * gb;
                    vb.y = acc[mi][ni][3] * gb;
                    *(float2*)(outa + ni * 8) = va;
                    *(float2*)(outb + ni * 8) = vb;
                    acc[mi][ni][0] = 0.f;
                    acc[mi][ni][1] = 0.f;
                    acc[mi][ni][2] = 0.f;
                    acc[mi][ni][3] = 0.f;
                }
            }
        }

        tile = s_tile[tslot ^ 1];
        tslot ^= 1;
    }
    #undef AADR
    #undef BADR
}

// ---------------------------------------------------------------------------
extern "C" void kernel_launch(void* const* d_in, const int* in_sizes, int n_in,
                              void* d_out, int out_size) {
    const float* x      = (const float*)d_in[0];
    const float* style  = (const float*)d_in[1];
    const float* weight = (const float*)d_in[2];
    const float* modw   = (const float*)d_in[3];
    const float* bias   = (const float*)d_in[4];
    float* out = (float*)d_out;

    cudaFuncSetAttribute(conv_main, cudaFuncAttributeMaxDynamicSharedMemorySize, SMEM_TOTAL);

    prep_sw<<<1024, 256>>>(style, modw, bias, weight);  // launch 0 (resets tile ctr)
    prep_xt<<<dim3(32, 8, 16), 256>>>(x);                // launch 1
    conv_main<<<NCTAS, NTHREADS, SMEM_TOTAL>>>(out);     // launch 2
}